// round 14
// baseline (speedup 1.0000x reference)
#include <cuda_runtime.h>
#include <cuda_fp16.h>
#include <math.h>
#include <stdint.h>

#define EMB 1024
#define NH  16
#define HD  64
#define BB  4
#define SS  2048
#define MT  (BB*SS)    // 8192 rows
#define NQKV 3072
#define KT16 (EMB/16)  // 64 k16-tiles per 1024

// Scratch (allocation-free rule: __device__ globals)
__device__ __half g_x[(size_t)MT*EMB];
__device__ __half g_qkv[(size_t)MT*NQKV];
__device__ __half g_o[(size_t)MT*EMB];
__device__ __half g_wqkv[(size_t)NQKV*EMB];
__device__ float  g_bqkv[NQKV];
__device__ __half g_wo[(size_t)EMB*EMB];

#define LOG2E 1.44269504088896f

__device__ __forceinline__ uint32_t h2u(float lo, float hi) {
    __half2 h = __floats2half2_rn(lo, hi);
    return *(uint32_t*)&h;
}
__device__ __forceinline__ uint32_t ex2h2(uint32_t x) {
    uint32_t r;
    asm("ex2.approx.f16x2 %0, %1;" : "=r"(r) : "r"(x));
    return r;
}

__device__ __forceinline__ void mma_f16(
    float& c0, float& c1, float& c2, float& c3,
    uint32_t a0, uint32_t a1, uint32_t a2, uint32_t a3,
    uint32_t b0, uint32_t b1)
{
    asm volatile(
        "mma.sync.aligned.m16n8k16.row.col.f32.f16.f16.f32 "
        "{%0,%1,%2,%3}, {%4,%5,%6,%7}, {%8,%9}, {%0,%1,%2,%3};"
        : "+f"(c0), "+f"(c1), "+f"(c2), "+f"(c3)
        : "r"(a0), "r"(a1), "r"(a2), "r"(a3), "r"(b0), "r"(b1));
}

__device__ __forceinline__ void ldsm4(
    uint32_t& r0, uint32_t& r1, uint32_t& r2, uint32_t& r3, uint32_t addr)
{
    asm volatile(
        "ldmatrix.sync.aligned.m8n8.x4.shared.b16 {%0,%1,%2,%3}, [%4];"
        : "=r"(r0), "=r"(r1), "=r"(r2), "=r"(r3) : "r"(addr));
}
__device__ __forceinline__ void ldsm4t(
    uint32_t& r0, uint32_t& r1, uint32_t& r2, uint32_t& r3, uint32_t addr)
{
    asm volatile(
        "ldmatrix.sync.aligned.m8n8.x4.trans.shared.b16 {%0,%1,%2,%3}, [%4];"
        : "=r"(r0), "=r"(r1), "=r"(r2), "=r"(r3) : "r"(addr));
}

__device__ __forceinline__ void cp16(uint32_t saddr, const void* gptr) {
    asm volatile("cp.async.cg.shared.global [%0], [%1], 16;\n"
                 :: "r"(saddr), "l"(gptr));
}
__device__ __forceinline__ void cp_commit() {
    asm volatile("cp.async.commit_group;\n");
}
template<int N> __device__ __forceinline__ void cp_wait() {
    asm volatile("cp.async.wait_group %0;\n" :: "n"(N));
}

// ---------------------------------------------------------------------------
// Packing kernels
// ---------------------------------------------------------------------------
__global__ void pack_a_kernel(const float* __restrict__ src,
                              __half* __restrict__ dst)
{
    int i = blockIdx.x * 256 + threadIdx.x;   // over MT*EMB
    int m = i >> 10, k = i & 1023;
    __half v = __float2half_rn(src[i]);
    int g = m & 7, d = (m >> 3) & 1;
    int kk = k & 15, hi = kk >> 3, jj = kk & 7, tig = jj >> 1, lo = jj & 1;
    size_t dest = (((size_t)(m >> 4) * KT16 + (k >> 4)) * 32 + g * 4 + tig) * 8
                + (hi * 2 + d) * 2 + lo;
    dst[dest] = v;
}

__global__ void pack_wqkv_kernel(
    const float* __restrict__ Wq, const float* __restrict__ Wk,
    const float* __restrict__ Wv,
    const float* __restrict__ bq, const float* __restrict__ bk,
    const float* __restrict__ bv,
    __half* __restrict__ Wp, float* __restrict__ bp)
{
    int i = blockIdx.x * 256 + threadIdx.x;   // over NQKV*EMB
    int n = i >> 10, k = i & 1023;
    float s = (n < 1024) ? (0.125f * LOG2E) : 1.0f;
    const float* W = (n < 1024) ? Wq : (n < 2048) ? Wk : Wv;
    __half v = __float2half_rn(W[(n & 1023) * 1024 + k] * s);
    int g = n & 7;
    int kk = k & 15, hi = kk >> 3, jj = kk & 7, tig = jj >> 1, lo = jj & 1;
    size_t dest = (((size_t)(n >> 3) * KT16 + (k >> 4)) * 32 + g * 4 + tig) * 4
                + hi * 2 + lo;
    Wp[dest] = v;
    if (i < NQKV) {
        const float* b = (i < 1024) ? bq : (i < 2048) ? bk : bv;
        bp[i] = ((i < 1024) ? (0.125f * LOG2E) : 1.0f) * b[i & 1023];
    }
}

__global__ void pack_wo_kernel(const float* __restrict__ W,
                               __half* __restrict__ Wp)
{
    int i = blockIdx.x * 256 + threadIdx.x;   // over EMB*EMB
    int n = i >> 10, k = i & 1023;
    __half v = __float2half_rn(W[i]);
    int g = n & 7;
    int kk = k & 15, hi = kk >> 3, jj = kk & 7, tig = jj >> 1, lo = jj & 1;
    size_t dest = (((size_t)(n >> 3) * KT16 + (k >> 4)) * 32 + g * 4 + tig) * 4
                + hi * 2 + lo;
    Wp[dest] = v;
}

// ---------------------------------------------------------------------------
// fp16 GEMM (m16n8k16), templated on pipeline depth & occupancy.
//   NS=3, OCC=2 (QKV): explicit 2-deep fragment prefetch (reg cap 256)
//   NS=2, OCC=3 (O-proj): single-buffer frags (reg cap 170)
// ---------------------------------------------------------------------------
#define ASTGB 16384
#define WSTGB 16384
#define GEMM_ITERS (EMB/64)

template<int NS, int OCC>
__global__ __launch_bounds__(128, OCC) void gemm_tc(
    const __half* __restrict__ A,
    const __half* __restrict__ W,
    const float* __restrict__ bias,
    void* __restrict__ Cv, int ldc, int out_half)
{
    extern __shared__ __align__(16) char smem[];
    char* As = smem;                      // [NS][ASTGB]
    char* Ws = smem + NS * ASTGB;         // [NS][WSTGB]

    const int tid  = threadIdx.x;
    const int w    = tid >> 5;
    const int lane = tid & 31;
    const int g    = lane >> 2;
    const int tig  = lane & 3;
    const int wm   = w >> 1;
    const int wn   = w & 1;
    const int m0   = blockIdx.y * 128;
    const int n0   = blockIdx.x * 128;
    const int m0t  = m0 >> 4;
    const int n0b  = n0 >> 3;

    uint32_t asb = (uint32_t)__cvta_generic_to_shared(As);
    uint32_t wsb = (uint32_t)__cvta_generic_to_shared(Ws);

    float acc[4][8][4];
#pragma unroll
    for (int mt = 0; mt < 4; mt++)
#pragma unroll
        for (int nt = 0; nt < 8; nt++)
#pragma unroll
            for (int j = 0; j < 4; j++) acc[mt][nt][j] = 0.0f;

    auto load_stage = [&](int st, int ktb) {
#pragma unroll
        for (int i = 0; i < 8; i++) {
            int idx = tid + i * 128;          // 0..1023 (16B chunks)
            int mt = idx >> 7, ra = idx & 127;
            int kta = ra >> 5, ca = ra & 31;
            cp16(asb + (uint32_t)(st * ASTGB + idx * 16),
                 A + ((size_t)(m0t + mt) * KT16 + ktb + kta) * 256 + ca * 8);
            int nb = idx >> 6, rw = idx & 63;
            int ktw = rw >> 4, cw = rw & 15;
            cp16(wsb + (uint32_t)(st * WSTGB + idx * 16),
                 W + ((size_t)(n0b + nb) * KT16 + ktb + ktw) * 128 + cw * 8);
        }
    };

#pragma unroll
    for (int s = 0; s < NS - 1; s++) {
        load_stage(s, s * 4);
        cp_commit();
    }

    for (int it = 0; it < GEMM_ITERS; it++) {
        const int st = it % NS;
        if (it + NS - 1 < GEMM_ITERS) cp_wait<NS - 2>(); else cp_wait<0>();
        __syncthreads();

        if (it + NS - 1 < GEMM_ITERS) {
            load_stage((it + NS - 1) % NS, (it + NS - 1) * 4);
            cp_commit();
        }

        const char* as = As + st * ASTGB;
        const char* ws = Ws + st * WSTGB;

        if constexpr (OCC == 2) {
            // explicit 2-deep fragment pipeline: load ks+1 before mma(ks)
            uint4 a4[2][4];
            uint2 b2[2][8];
            auto ldf = [&](int buf, int ks) {
#pragma unroll
                for (int mt = 0; mt < 4; mt++)
                    a4[buf][mt] = *(const uint4*)(as + (((wm * 4 + mt) * 4 + ks) * 32 + lane) * 16);
#pragma unroll
                for (int nt = 0; nt < 8; nt++)
                    b2[buf][nt] = *(const uint2*)(ws + (((wn * 8 + nt) * 4 + ks) * 32 + lane) * 8);
            };
            ldf(0, 0);
#pragma unroll
            for (int ks = 0; ks < 4; ks++) {
                if (ks < 3) ldf((ks + 1) & 1, ks + 1);
                const int cb = ks & 1;
#pragma unroll
                for (int nt = 0; nt < 8; nt++)
#pragma unroll
                    for (int mt = 0; mt < 4; mt++)
                        mma_f16(acc[mt][nt][0], acc[mt][nt][1],
                                acc[mt][nt][2], acc[mt][nt][3],
                                a4[cb][mt].x, a4[cb][mt].y,
                                a4[cb][mt].z, a4[cb][mt].w,
                                b2[cb][nt].x, b2[cb][nt].y);
            }
        } else {
            // reg-lean path for OCC=3
#pragma unroll
            for (int ks = 0; ks < 4; ks++) {
                uint4 a4[4];
#pragma unroll
                for (int mt = 0; mt < 4; mt++)
                    a4[mt] = *(const uint4*)(as + (((wm * 4 + mt) * 4 + ks) * 32 + lane) * 16);
#pragma unroll
                for (int nt = 0; nt < 8; nt++) {
                    uint2 b2 = *(const uint2*)(ws + (((wn * 8 + nt) * 4 + ks) * 32 + lane) * 8);
#pragma unroll
                    for (int mt = 0; mt < 4; mt++)
                        mma_f16(acc[mt][nt][0], acc[mt][nt][1],
                                acc[mt][nt][2], acc[mt][nt][3],
                                a4[mt].x, a4[mt].y, a4[mt].z, a4[mt].w,
                                b2.x, b2.y);
                }
            }
        }
    }

    // Epilogue with bias
#pragma unroll
    for (int mt = 0; mt < 4; mt++) {
#pragma unroll
        for (int nt = 0; nt < 8; nt++) {
            const int ng  = n0 + wn * 64 + nt * 8 + 2 * tig;
            const int row = m0 + wm * 64 + mt * 16 + g;
            float2 bv = *(const float2*)(bias + ng);
            float o00 = acc[mt][nt][0] + bv.x;
            float o01 = acc[mt][nt][1] + bv.y;
            float o10 = acc[mt][nt][2] + bv.x;
            float o11 = acc[mt][nt][3] + bv.y;
            if (out_half) {
                __half* C = (__half*)Cv;
                *(__half2*)(C + (size_t)row * ldc + ng) =
                    __floats2half2_rn(o00, o01);
                *(__half2*)(C + (size_t)(row + 8) * ldc + ng) =
                    __floats2half2_rn(o10, o11);
            } else {
                float* C = (float*)Cv;
                *(float2*)(C + (size_t)row * ldc + ng) = make_float2(o00, o01);
                *(float2*)(C + (size_t)(row + 8) * ldc + ng) = make_float2(o10, o11);
            }
        }
    }
}

// ---------------------------------------------------------------------------
// Flash attention, fp16 mma, software-pipelined ldmatrix:
// per 16-key slice: [V-ldsm x4][QK mma x16][ex2 + ones][K-ldsm(np+1) x4]
// [PV mma x16]. Every ldmatrix has >=16 mmas of latency cover (volatile
// asm order is preserved, so this ordering is enforced).
// 128-key double-buffered tiles, 3 CTAs/SM.
// ---------------------------------------------------------------------------
#define KVSTR 72
#define KVROWB (KVSTR*2)
#define TILEB (128*KVROWB)          // 18432 B per 128-key tile
#define ATTN_SMEM (4*TILEB)         // K0,K1,V0,V1 = 73728 B
#define ONES16 0x3C003C00u

__global__ __launch_bounds__(128, 3) void attn_tc()
{
    extern __shared__ __align__(16) char sm[];

    const int tid  = threadIdx.x;
    const int w    = tid >> 5;
    const int lane = tid & 31;
    const int g    = lane >> 2;
    const int tig  = lane & 3;
    const int s0   = blockIdx.x * 128;
    const int h    = blockIdx.y;
    const int b    = blockIdx.z;
    const size_t baseQ = (size_t)b * SS * NQKV + (size_t)h * HD;
    const size_t baseK = baseQ + 1024;
    const size_t baseV = baseQ + 2048;
    const int mrow = w * 32;

    uint32_t smb = (uint32_t)__cvta_generic_to_shared(sm);
    const uint32_t ksb[2] = {smb, smb + TILEB};
    const uint32_t vsb[2] = {smb + 2 * TILEB, smb + 3 * TILEB};

    const uint32_t k_lane = (uint32_t)(((lane >> 4) * 8 + (lane & 7)) * KVROWB
                                       + ((lane >> 3) & 1) * 16);
    const uint32_t v_lane = (uint32_t)((((lane >> 3) & 1) * 8 + (lane & 7)) * KVROWB
                                       + (lane >> 4) * 16);

    // Q fragments (loop-invariant)
    uint32_t qa[2][4][4];
#pragma unroll
    for (int t = 0; t < 2; t++) {
        const __half* q0 = g_qkv + baseQ + (size_t)(s0 + mrow + t * 16 + g) * NQKV;
        const __half* q1 = g_qkv + baseQ + (size_t)(s0 + mrow + t * 16 + 8 + g) * NQKV;
#pragma unroll
        for (int kt = 0; kt < 4; kt++) {
            qa[t][kt][0] = *(const uint32_t*)(q0 + kt * 16 + 2 * tig);
            qa[t][kt][1] = *(const uint32_t*)(q1 + kt * 16 + 2 * tig);
            qa[t][kt][2] = *(const uint32_t*)(q0 + kt * 16 + 2 * tig + 8);
            qa[t][kt][3] = *(const uint32_t*)(q1 + kt * 16 + 2 * tig + 8);
        }
    }

    auto load_tile = [&](int buf, int kt0) {
#pragma unroll
        for (int i = 0; i < 8; i++) {
            int idx = tid + i * 128;           // 0..1023
            int r = idx >> 3;                  // 0..127
            int c = idx & 7;
            cp16(ksb[buf] + (uint32_t)(r * KVROWB + c * 16),
                 g_qkv + baseK + (size_t)(kt0 + r) * NQKV + c * 8);
            cp16(vsb[buf] + (uint32_t)(r * KVROWB + c * 16),
                 g_qkv + baseV + (size_t)(kt0 + r) * NQKV + c * 8);
        }
    };

    load_tile(0, 0);
    cp_commit();

    float o[2][8][4];
#pragma unroll
    for (int t = 0; t < 2; t++)
#pragma unroll
        for (int nt = 0; nt < 8; nt++)
#pragma unroll
            for (int j = 0; j < 4; j++) o[t][nt][j] = 0.0f;
    float osum[2][4] = {{0,0,0,0},{0,0,0,0}};

    for (int kt0 = 0; kt0 < SS; kt0 += 128) {
        const int st = (kt0 >> 7) & 1;
        cp_wait<0>();
        __syncthreads();

        if (kt0 + 128 < SS) {
            load_tile(st ^ 1, kt0 + 128);
            cp_commit();
        }

        // preload K fragments for np = 0
        uint32_t kf[4][4];
#pragma unroll
        for (int kt = 0; kt < 4; kt++)
            ldsm4(kf[kt][0], kf[kt][1], kf[kt][2], kf[kt][3],
                  ksb[st] + (uint32_t)(kt * 32) + k_lane);

#pragma unroll
        for (int np = 0; np < 8; np++) {
            // 1) V fragments for this slice (hidden under the QK mmas below)
            uint32_t vf[4][4];
#pragma unroll
            for (int nbp = 0; nbp < 4; nbp++)
                ldsm4t(vf[nbp][0], vf[nbp][1], vf[nbp][2], vf[nbp][3],
                       vsb[st] + (uint32_t)(np * 16 * KVROWB + nbp * 32) + v_lane);

            // 2) QK mmas using preloaded kf
            float s[2][2][4];
#pragma unroll
            for (int t = 0; t < 2; t++)
#pragma unroll
                for (int p = 0; p < 2; p++)
#pragma unroll
                    for (int j = 0; j < 4; j++) s[t][p][j] = 0.0f;

#pragma unroll
            for (int kt = 0; kt < 4; kt++) {
                mma_f16(s[0][0][0], s[0][0][1], s[0][0][2], s[0][0][3],
                        qa[0][kt][0], qa[0][kt][1], qa[0][kt][2], qa[0][kt][3],
                        kf[kt][0], kf[kt][1]);
                mma_f16(s[1][0][0], s[1][0][1], s[1][0][2], s[1][0][3],
                        qa[1][kt][0], qa[1][kt][1], qa[1][kt][2], qa[1][kt][3],
                        kf[kt][0], kf[kt][1]);
                mma_f16(s[0][1][0], s[0][1][1], s[0][1][2], s[0][1][3],
                        qa[0][kt][0], qa[0][kt][1], qa[0][kt][2], qa[0][kt][3],
                        kf[kt][2], kf[kt][3]);
                mma_f16(s[1][1][0], s[1][1][1], s[1][1][2], s[1][1][3],
                        qa[1][kt][0], qa[1][kt][1], qa[1][kt][2], qa[1][kt][3],
                        kf[kt][2], kf[kt][3]);
            }

            // 3) P = 2^S (fp16x2) + ones-mma row sums
            uint32_t pa[2][4];
#pragma unroll
            for (int t = 0; t < 2; t++) {
                pa[t][0] = ex2h2(h2u(s[t][0][0], s[t][0][1]));
                pa[t][1] = ex2h2(h2u(s[t][0][2], s[t][0][3]));
                pa[t][2] = ex2h2(h2u(s[t][1][0], s[t][1][1]));
                pa[t][3] = ex2h2(h2u(s[t][1][2], s[t][1][3]));
                mma_f16(osum[t][0], osum[t][1], osum[t][2], osum[t][3],
                        pa[t][0], pa[t][1], pa[t][2], pa[t][3],
                        ONES16, ONES16);
            }

            // 4) K fragments for np+1 (hidden under the PV mmas below)
            if (np < 7) {
#pragma unroll
                for (int kt = 0; kt < 4; kt++)
                    ldsm4(kf[kt][0], kf[kt][1], kf[kt][2], kf[kt][3],
                          ksb[st] + (uint32_t)((np + 1) * 16 * KVROWB + kt * 32)
                                  + k_lane);
            }

            // 5) PV mmas using vf
#pragma unroll
            for (int nbp = 0; nbp < 4; nbp++) {
                mma_f16(o[0][2*nbp][0], o[0][2*nbp][1], o[0][2*nbp][2], o[0][2*nbp][3],
                        pa[0][0], pa[0][1], pa[0][2], pa[0][3],
                        vf[nbp][0], vf[nbp][1]);
                mma_f16(o[1][2*nbp][0], o[1][2*nbp][1], o[1][2*nbp][2], o[1][2*nbp][3],
                        pa[1][0], pa[1][1], pa[1][2], pa[1][3],
                        vf[nbp][0], vf[nbp][1]);
                mma_f16(o[0][2*nbp+1][0], o[0][2*nbp+1][1], o[0][2*nbp+1][2], o[0][2*nbp+1][3],
                        pa[0][0], pa[0][1], pa[0][2], pa[0][3],
                        vf[nbp][2], vf[nbp][3]);
                mma_f16(o[1][2*nbp+1][0], o[1][2*nbp+1][1], o[1][2*nbp+1][2], o[1][2*nbp+1][3],
                        pa[1][0], pa[1][1], pa[1][2], pa[1][3],
                        vf[nbp][2], vf[nbp][3]);
            }
        }
    }

    // Normalize (row sums in osum: c0 = row g, c2 = row g+8), write O packed
#pragma unroll
    for (int t = 0; t < 2; t++) {
        const float inv0 = 1.0f / osum[t][0];
        const float inv1 = 1.0f / osum[t][2];
        const int m = b * SS + s0 + mrow + t * 16 + g;
        const size_t mtile = (size_t)(m >> 4);
#pragma unroll
        for (int nt = 0; nt < 8; nt++) {
            size_t hidx = ((mtile * KT16 + h * 4 + (nt >> 1)) * 32
                           + g * 4 + tig) * 8 + (nt & 1) * 4;
            uint2 val;
            val.x = h2u(o[t][nt][0] * inv0, o[t][nt][1] * inv0);
            val.y = h2u(o[t][nt][2] * inv1, o[t][nt][3] * inv1);
            *(uint2*)(g_o + hidx) = val;
        }
    }
}

// ---------------------------------------------------------------------------
extern "C" void kernel_launch(void* const* d_in, const int* in_sizes, int n_in,
                              void* d_out, int out_size)
{
    const float* x  = (const float*)d_in[0];
    const float* Wq = (const float*)d_in[1];
    const float* bq = (const float*)d_in[2];
    const float* Wk = (const float*)d_in[3];
    const float* bk = (const float*)d_in[4];
    const float* Wv = (const float*)d_in[5];
    const float* bv = (const float*)d_in[6];
    const float* Wo = (const float*)d_in[7];
    const float* bo = (const float*)d_in[8];

    __half *gx, *qkv, *o, *wqkv, *wo;
    float *bqkv;
    cudaGetSymbolAddress((void**)&gx,   g_x);
    cudaGetSymbolAddress((void**)&qkv,  g_qkv);
    cudaGetSymbolAddress((void**)&o,    g_o);
    cudaGetSymbolAddress((void**)&wqkv, g_wqkv);
    cudaGetSymbolAddress((void**)&bqkv, g_bqkv);
    cudaGetSymbolAddress((void**)&wo,   g_wo);

    const int SM3 = 3 * (ASTGB + WSTGB);   // 98304
    const int SM2 = 2 * (ASTGB + WSTGB);   // 65536
    cudaFuncSetAttribute(gemm_tc<3,2>,
                         cudaFuncAttributeMaxDynamicSharedMemorySize, SM3);
    cudaFuncSetAttribute(gemm_tc<2,3>,
                         cudaFuncAttributeMaxDynamicSharedMemorySize, SM2);
    cudaFuncSetAttribute(attn_tc,
                         cudaFuncAttributeMaxDynamicSharedMemorySize, ATTN_SMEM);

    pack_a_kernel<<<(MT * EMB) / 256, 256>>>(x, gx);
    pack_wqkv_kernel<<<(NQKV * EMB) / 256, 256>>>(Wq, Wk, Wv, bq, bk, bv,
                                                  wqkv, bqkv);
    pack_wo_kernel<<<(EMB * EMB) / 256, 256>>>(Wo, wo);

    // Fused QKV projection: [8192 x 3072], fp16 out — 3-stage, 2 CTA/SM
    gemm_tc<3,2><<<dim3(NQKV / 128, MT / 128), 128, SM3>>>(
        gx, wqkv, bqkv, qkv, NQKV, 1);

    attn_tc<<<dim3(SS / 128, NH, BB), 128, ATTN_SMEM>>>();

    // Output projection: fp32 out — 2-stage, 3 CTA/SM (tail-wave friendly)
    gemm_tc<2,3><<<dim3(EMB / 128, MT / 128), 128, SM2>>>(
        o, wo, bo, d_out, EMB, 0);
}

// round 15
// speedup vs baseline: 1.0754x; 1.0754x over previous
#include <cuda_runtime.h>
#include <cuda_fp16.h>
#include <math.h>
#include <stdint.h>

#define EMB 1024
#define NH  16
#define HD  64
#define BB  4
#define SS  2048
#define MT  (BB*SS)    // 8192 rows
#define NQKV 3072
#define KT16 (EMB/16)  // 64 k16-tiles per 1024

// Scratch (allocation-free rule: __device__ globals)
__device__ __half g_x[(size_t)MT*EMB];
__device__ __half g_qkv[(size_t)MT*NQKV];
__device__ __half g_o[(size_t)MT*EMB];
__device__ __half g_wqkv[(size_t)NQKV*EMB];
__device__ float  g_bqkv[NQKV];
__device__ __half g_wo[(size_t)EMB*EMB];

#define LOG2E 1.44269504088896f

__device__ __forceinline__ uint32_t h2u(float lo, float hi) {
    __half2 h = __floats2half2_rn(lo, hi);
    return *(uint32_t*)&h;
}
__device__ __forceinline__ uint32_t ex2h2(uint32_t x) {
    uint32_t r;
    asm("ex2.approx.f16x2 %0, %1;" : "=r"(r) : "r"(x));
    return r;
}

__device__ __forceinline__ void mma_f16(
    float& c0, float& c1, float& c2, float& c3,
    uint32_t a0, uint32_t a1, uint32_t a2, uint32_t a3,
    uint32_t b0, uint32_t b1)
{
    asm volatile(
        "mma.sync.aligned.m16n8k16.row.col.f32.f16.f16.f32 "
        "{%0,%1,%2,%3}, {%4,%5,%6,%7}, {%8,%9}, {%0,%1,%2,%3};"
        : "+f"(c0), "+f"(c1), "+f"(c2), "+f"(c3)
        : "r"(a0), "r"(a1), "r"(a2), "r"(a3), "r"(b0), "r"(b1));
}

__device__ __forceinline__ void ldsm4(
    uint32_t& r0, uint32_t& r1, uint32_t& r2, uint32_t& r3, uint32_t addr)
{
    asm volatile(
        "ldmatrix.sync.aligned.m8n8.x4.shared.b16 {%0,%1,%2,%3}, [%4];"
        : "=r"(r0), "=r"(r1), "=r"(r2), "=r"(r3) : "r"(addr));
}
__device__ __forceinline__ void ldsm4t(
    uint32_t& r0, uint32_t& r1, uint32_t& r2, uint32_t& r3, uint32_t addr)
{
    asm volatile(
        "ldmatrix.sync.aligned.m8n8.x4.trans.shared.b16 {%0,%1,%2,%3}, [%4];"
        : "=r"(r0), "=r"(r1), "=r"(r2), "=r"(r3) : "r"(addr));
}

__device__ __forceinline__ void cp16(uint32_t saddr, const void* gptr) {
    asm volatile("cp.async.cg.shared.global [%0], [%1], 16;\n"
                 :: "r"(saddr), "l"(gptr));
}
__device__ __forceinline__ void cp_commit() {
    asm volatile("cp.async.commit_group;\n");
}
template<int N> __device__ __forceinline__ void cp_wait() {
    asm volatile("cp.async.wait_group %0;\n" :: "n"(N));
}

// ---------------------------------------------------------------------------
// Packing kernels — DEST-ORDER, vectorized stores (uint4 / uint2).
// A-pack layout: chunk c = ((mtile*KT16 + kt)*32 + lane), lane = g*4+tig.
//   half j of chunk: (hi*2+d)*2+lo, with m = mtile*16 + d*8 + g,
//   k = kt*16 + hi*8 + tig*2 + lo.
// ---------------------------------------------------------------------------
__global__ void pack_a_kernel(const float* __restrict__ src,
                              __half* __restrict__ dst)
{
    int c = blockIdx.x * 256 + threadIdx.x;   // over MT*EMB/8 chunks
    int lane = c & 31;
    int kt   = (c >> 5) & (KT16 - 1);
    int mt   = c >> 11;                        // c / (32*KT16)
    int g = lane >> 2, tig = lane & 3;
    int m0 = mt * 16 + g;                      // d=0 row
    int k0 = kt * 16 + tig * 2;

    const float* r0 = src + (size_t)m0 * EMB + k0;        // d=0
    const float* r1 = src + (size_t)(m0 + 8) * EMB + k0;  // d=1
    float2 a00 = *(const float2*)(r0);        // hi=0, d=0 : lo 0,1
    float2 a01 = *(const float2*)(r0 + 8);    // hi=1, d=0
    float2 a10 = *(const float2*)(r1);        // hi=0, d=1
    float2 a11 = *(const float2*)(r1 + 8);    // hi=1, d=1

    uint4 out;
    out.x = h2u(a00.x, a00.y);   // (hi0,d0): lo0, lo1
    out.y = h2u(a10.x, a10.y);   // (hi0,d1)
    out.z = h2u(a01.x, a01.y);   // (hi1,d0)
    out.w = h2u(a11.x, a11.y);   // (hi1,d1)
    *(uint4*)(dst + (size_t)c * 8) = out;
}

// W-pack: chunk c = ((nb*KT16 + kt)*32 + lane); 4 halves: hi*2+lo,
//   n = nb*8+g, k = kt*16 + hi*8 + tig*2 + lo.
__global__ void pack_wqkv_kernel(
    const float* __restrict__ Wq, const float* __restrict__ Wk,
    const float* __restrict__ Wv,
    const float* __restrict__ bq, const float* __restrict__ bk,
    const float* __restrict__ bv,
    __half* __restrict__ Wp, float* __restrict__ bp)
{
    int c = blockIdx.x * 256 + threadIdx.x;   // over NQKV*EMB/4 chunks
    int lane = c & 31;
    int kt   = (c >> 5) & (KT16 - 1);
    int nb   = c >> 11;
    int g = lane >> 2, tig = lane & 3;
    int n = nb * 8 + g;
    float s = (n < 1024) ? (0.125f * LOG2E) : 1.0f;
    const float* W = (n < 1024) ? Wq : (n < 2048) ? Wk : Wv;
    const float* row = W + (size_t)(n & 1023) * 1024 + kt * 16 + tig * 2;
    float2 w0 = *(const float2*)(row);        // hi=0: lo 0,1
    float2 w1 = *(const float2*)(row + 8);    // hi=1
    uint2 out;
    out.x = h2u(w0.x * s, w0.y * s);
    out.y = h2u(w1.x * s, w1.y * s);
    *(uint2*)(Wp + (size_t)c * 4) = out;

    if (c < NQKV) {
        const float* b = (c < 1024) ? bq : (c < 2048) ? bk : bv;
        bp[c] = ((c < 1024) ? (0.125f * LOG2E) : 1.0f) * b[c & 1023];
    }
}

__global__ void pack_wo_kernel(const float* __restrict__ W,
                               __half* __restrict__ Wp)
{
    int c = blockIdx.x * 256 + threadIdx.x;   // over EMB*EMB/4 chunks
    int lane = c & 31;
    int kt   = (c >> 5) & (KT16 - 1);
    int nb   = c >> 11;
    int g = lane >> 2, tig = lane & 3;
    const float* row = W + (size_t)(nb * 8 + g) * 1024 + kt * 16 + tig * 2;
    float2 w0 = *(const float2*)(row);
    float2 w1 = *(const float2*)(row + 8);
    uint2 out;
    out.x = h2u(w0.x, w0.y);
    out.y = h2u(w1.x, w1.y);
    *(uint2*)(Wp + (size_t)c * 4) = out;
}

// ---------------------------------------------------------------------------
// fp16 GEMM (m16n8k16), templated on pipeline depth & occupancy (R13 form).
//   NS=3, OCC=2 (QKV, 5.2 waves); NS=2, OCC=3 (O-proj, 1.15 waves).
// CTA 128x128, BK=64, 128 thr = 4 warps (2x2), warp tile 64x64.
// ---------------------------------------------------------------------------
#define ASTGB 16384
#define WSTGB 16384
#define GEMM_ITERS (EMB/64)

template<int NS, int OCC>
__global__ __launch_bounds__(128, OCC) void gemm_tc(
    const __half* __restrict__ A,
    const __half* __restrict__ W,
    const float* __restrict__ bias,
    void* __restrict__ Cv, int ldc, int out_half)
{
    extern __shared__ __align__(16) char smem[];
    char* As = smem;                      // [NS][ASTGB]
    char* Ws = smem + NS * ASTGB;         // [NS][WSTGB]

    const int tid  = threadIdx.x;
    const int w    = tid >> 5;
    const int lane = tid & 31;
    const int g    = lane >> 2;
    const int tig  = lane & 3;
    const int wm   = w >> 1;
    const int wn   = w & 1;
    const int m0   = blockIdx.y * 128;
    const int n0   = blockIdx.x * 128;
    const int m0t  = m0 >> 4;
    const int n0b  = n0 >> 3;

    uint32_t asb = (uint32_t)__cvta_generic_to_shared(As);
    uint32_t wsb = (uint32_t)__cvta_generic_to_shared(Ws);

    float acc[4][8][4];
#pragma unroll
    for (int mt = 0; mt < 4; mt++)
#pragma unroll
        for (int nt = 0; nt < 8; nt++)
#pragma unroll
            for (int j = 0; j < 4; j++) acc[mt][nt][j] = 0.0f;

    auto load_stage = [&](int st, int ktb) {
#pragma unroll
        for (int i = 0; i < 8; i++) {
            int idx = tid + i * 128;          // 0..1023 (16B chunks)
            int mt = idx >> 7, ra = idx & 127;
            int kta = ra >> 5, ca = ra & 31;
            cp16(asb + (uint32_t)(st * ASTGB + idx * 16),
                 A + ((size_t)(m0t + mt) * KT16 + ktb + kta) * 256 + ca * 8);
            int nb = idx >> 6, rw = idx & 63;
            int ktw = rw >> 4, cw = rw & 15;
            cp16(wsb + (uint32_t)(st * WSTGB + idx * 16),
                 W + ((size_t)(n0b + nb) * KT16 + ktb + ktw) * 128 + cw * 8);
        }
    };

#pragma unroll
    for (int s = 0; s < NS - 1; s++) {
        load_stage(s, s * 4);
        cp_commit();
    }

    for (int it = 0; it < GEMM_ITERS; it++) {
        const int st = it % NS;
        if (it + NS - 1 < GEMM_ITERS) cp_wait<NS - 2>(); else cp_wait<0>();
        __syncthreads();

        if (it + NS - 1 < GEMM_ITERS) {
            load_stage((it + NS - 1) % NS, (it + NS - 1) * 4);
            cp_commit();
        }

        const char* as = As + st * ASTGB;
        const char* ws = Ws + st * WSTGB;
#pragma unroll
        for (int ks = 0; ks < 4; ks++) {
            uint4 a4[4];
#pragma unroll
            for (int mt = 0; mt < 4; mt++)
                a4[mt] = *(const uint4*)(as + (((wm * 4 + mt) * 4 + ks) * 32
                                             + lane) * 16);
#pragma unroll
            for (int nt = 0; nt < 8; nt++) {
                uint2 b2 = *(const uint2*)(ws + (((wn * 8 + nt) * 4 + ks) * 32
                                              + lane) * 8);
#pragma unroll
                for (int mt = 0; mt < 4; mt++)
                    mma_f16(acc[mt][nt][0], acc[mt][nt][1],
                            acc[mt][nt][2], acc[mt][nt][3],
                            a4[mt].x, a4[mt].y, a4[mt].z, a4[mt].w,
                            b2.x, b2.y);
            }
        }
    }

    // Epilogue with bias
#pragma unroll
    for (int mt = 0; mt < 4; mt++) {
#pragma unroll
        for (int nt = 0; nt < 8; nt++) {
            const int ng  = n0 + wn * 64 + nt * 8 + 2 * tig;
            const int row = m0 + wm * 64 + mt * 16 + g;
            float2 bv = *(const float2*)(bias + ng);
            float o00 = acc[mt][nt][0] + bv.x;
            float o01 = acc[mt][nt][1] + bv.y;
            float o10 = acc[mt][nt][2] + bv.x;
            float o11 = acc[mt][nt][3] + bv.y;
            if (out_half) {
                __half* C = (__half*)Cv;
                *(__half2*)(C + (size_t)row * ldc + ng) =
                    __floats2half2_rn(o00, o01);
                *(__half2*)(C + (size_t)(row + 8) * ldc + ng) =
                    __floats2half2_rn(o10, o11);
            } else {
                float* C = (float*)Cv;
                *(float2*)(C + (size_t)row * ldc + ng) = make_float2(o00, o01);
                *(float2*)(C + (size_t)(row + 8) * ldc + ng) = make_float2(o10, o11);
            }
        }
    }
}

// ---------------------------------------------------------------------------
// Flash attention, fp16 mma (R13 form). Fused per-16-key-slice pipeline
// (QK -> ex2 -> PV + ones-mma). 128-key double-buffered tiles, 3 CTAs/SM.
// ---------------------------------------------------------------------------
#define KVSTR 72
#define KVROWB (KVSTR*2)
#define TILEB (128*KVROWB)          // 18432 B per 128-key tile
#define ATTN_SMEM (4*TILEB)         // K0,K1,V0,V1 = 73728 B
#define ONES16 0x3C003C00u

__global__ __launch_bounds__(128, 3) void attn_tc()
{
    extern __shared__ __align__(16) char sm[];

    const int tid  = threadIdx.x;
    const int w    = tid >> 5;
    const int lane = tid & 31;
    const int g    = lane >> 2;
    const int tig  = lane & 3;
    const int s0   = blockIdx.x * 128;
    const int h    = blockIdx.y;
    const int b    = blockIdx.z;
    const size_t baseQ = (size_t)b * SS * NQKV + (size_t)h * HD;
    const size_t baseK = baseQ + 1024;
    const size_t baseV = baseQ + 2048;
    const int mrow = w * 32;

    uint32_t smb = (uint32_t)__cvta_generic_to_shared(sm);
    const uint32_t ksb[2] = {smb, smb + TILEB};
    const uint32_t vsb[2] = {smb + 2 * TILEB, smb + 3 * TILEB};

    const uint32_t k_lane = (uint32_t)(((lane >> 4) * 8 + (lane & 7)) * KVROWB
                                       + ((lane >> 3) & 1) * 16);
    const uint32_t v_lane = (uint32_t)((((lane >> 3) & 1) * 8 + (lane & 7)) * KVROWB
                                       + (lane >> 4) * 16);

    // Q fragments (loop-invariant)
    uint32_t qa[2][4][4];
#pragma unroll
    for (int t = 0; t < 2; t++) {
        const __half* q0 = g_qkv + baseQ + (size_t)(s0 + mrow + t * 16 + g) * NQKV;
        const __half* q1 = g_qkv + baseQ + (size_t)(s0 + mrow + t * 16 + 8 + g) * NQKV;
#pragma unroll
        for (int kt = 0; kt < 4; kt++) {
            qa[t][kt][0] = *(const uint32_t*)(q0 + kt * 16 + 2 * tig);
            qa[t][kt][1] = *(const uint32_t*)(q1 + kt * 16 + 2 * tig);
            qa[t][kt][2] = *(const uint32_t*)(q0 + kt * 16 + 2 * tig + 8);
            qa[t][kt][3] = *(const uint32_t*)(q1 + kt * 16 + 2 * tig + 8);
        }
    }

    auto load_tile = [&](int buf, int kt0) {
#pragma unroll
        for (int i = 0; i < 8; i++) {
            int idx = tid + i * 128;           // 0..1023
            int r = idx >> 3;                  // 0..127
            int c = idx & 7;
            cp16(ksb[buf] + (uint32_t)(r * KVROWB + c * 16),
                 g_qkv + baseK + (size_t)(kt0 + r) * NQKV + c * 8);
            cp16(vsb[buf] + (uint32_t)(r * KVROWB + c * 16),
                 g_qkv + baseV + (size_t)(kt0 + r) * NQKV + c * 8);
        }
    };

    load_tile(0, 0);
    cp_commit();

    float o[2][8][4];
#pragma unroll
    for (int t = 0; t < 2; t++)
#pragma unroll
        for (int nt = 0; nt < 8; nt++)
#pragma unroll
            for (int j = 0; j < 4; j++) o[t][nt][j] = 0.0f;
    float osum[2][4] = {{0,0,0,0},{0,0,0,0}};

    for (int kt0 = 0; kt0 < SS; kt0 += 128) {
        const int st = (kt0 >> 7) & 1;
        cp_wait<0>();
        __syncthreads();

        if (kt0 + 128 < SS) {
            load_tile(st ^ 1, kt0 + 128);
            cp_commit();
        }

        // fused per-16-key slice: QK -> ex2 -> PV (+row-sum mma)
#pragma unroll
        for (int np = 0; np < 8; np++) {
            float s[2][2][4];
#pragma unroll
            for (int t = 0; t < 2; t++)
#pragma unroll
                for (int p = 0; p < 2; p++)
#pragma unroll
                    for (int j = 0; j < 4; j++) s[t][p][j] = 0.0f;

#pragma unroll
            for (int kt = 0; kt < 4; kt++) {
                uint32_t b0, b1, b2, b3;
                ldsm4(b0, b1, b2, b3,
                      ksb[st] + (uint32_t)(np * 16 * KVROWB + kt * 32) + k_lane);
                mma_f16(s[0][0][0], s[0][0][1], s[0][0][2], s[0][0][3],
                        qa[0][kt][0], qa[0][kt][1], qa[0][kt][2], qa[0][kt][3],
                        b0, b1);
                mma_f16(s[1][0][0], s[1][0][1], s[1][0][2], s[1][0][3],
                        qa[1][kt][0], qa[1][kt][1], qa[1][kt][2], qa[1][kt][3],
                        b0, b1);
                mma_f16(s[0][1][0], s[0][1][1], s[0][1][2], s[0][1][3],
                        qa[0][kt][0], qa[0][kt][1], qa[0][kt][2], qa[0][kt][3],
                        b2, b3);
                mma_f16(s[1][1][0], s[1][1][1], s[1][1][2], s[1][1][3],
                        qa[1][kt][0], qa[1][kt][1], qa[1][kt][2], qa[1][kt][3],
                        b2, b3);
            }

            uint32_t pa[2][4];
#pragma unroll
            for (int t = 0; t < 2; t++) {
                pa[t][0] = ex2h2(h2u(s[t][0][0], s[t][0][1]));
                pa[t][1] = ex2h2(h2u(s[t][0][2], s[t][0][3]));
                pa[t][2] = ex2h2(h2u(s[t][1][0], s[t][1][1]));
                pa[t][3] = ex2h2(h2u(s[t][1][2], s[t][1][3]));
                mma_f16(osum[t][0], osum[t][1], osum[t][2], osum[t][3],
                        pa[t][0], pa[t][1], pa[t][2], pa[t][3],
                        ONES16, ONES16);
            }

#pragma unroll
            for (int nbp = 0; nbp < 4; nbp++) {
                uint32_t b0, b1, b2, b3;
                ldsm4t(b0, b1, b2, b3,
                       vsb[st] + (uint32_t)(np * 16 * KVROWB + nbp * 32) + v_lane);
                mma_f16(o[0][2*nbp][0], o[0][2*nbp][1], o[0][2*nbp][2], o[0][2*nbp][3],
                        pa[0][0], pa[0][1], pa[0][2], pa[0][3], b0, b1);
                mma_f16(o[1][2*nbp][0], o[1][2*nbp][1], o[1][2*nbp][2], o[1][2*nbp][3],
                        pa[1][0], pa[1][1], pa[1][2], pa[1][3], b0, b1);
                mma_f16(o[0][2*nbp+1][0], o[0][2*nbp+1][1], o[0][2*nbp+1][2], o[0][2*nbp+1][3],
                        pa[0][0], pa[0][1], pa[0][2], pa[0][3], b2, b3);
                mma_f16(o[1][2*nbp+1][0], o[1][2*nbp+1][1], o[1][2*nbp+1][2], o[1][2*nbp+1][3],
                        pa[1][0], pa[1][1], pa[1][2], pa[1][3], b2, b3);
            }
        }
    }

    // Normalize (row sums in osum: c0 = row g, c2 = row g+8), write O packed
#pragma unroll
    for (int t = 0; t < 2; t++) {
        const float inv0 = 1.0f / osum[t][0];
        const float inv1 = 1.0f / osum[t][2];
        const int m = b * SS + s0 + mrow + t * 16 + g;
        const size_t mtile = (size_t)(m >> 4);
#pragma unroll
        for (int nt = 0; nt < 8; nt++) {
            size_t hidx = ((mtile * KT16 + h * 4 + (nt >> 1)) * 32
                           + g * 4 + tig) * 8 + (nt & 1) * 4;
            uint2 val;
            val.x = h2u(o[t][nt][0] * inv0, o[t][nt][1] * inv0);
            val.y = h2u(o[t][nt][2] * inv1, o[t][nt][3] * inv1);
            *(uint2*)(g_o + hidx) = val;
        }
    }
}

// ---------------------------------------------------------------------------
extern "C" void kernel_launch(void* const* d_in, const int* in_sizes, int n_in,
                              void* d_out, int out_size)
{
    const float* x  = (const float*)d_in[0];
    const float* Wq = (const float*)d_in[1];
    const float* bq = (const float*)d_in[2];
    const float* Wk = (const float*)d_in[3];
    const float* bk = (const float*)d_in[4];
    const float* Wv = (const float*)d_in[5];
    const float* bv = (const float*)d_in[6];
    const float* Wo = (const float*)d_in[7];
    const float* bo = (const float*)d_in[8];

    __half *gx, *qkv, *o, *wqkv, *wo;
    float *bqkv;
    cudaGetSymbolAddress((void**)&gx,   g_x);
    cudaGetSymbolAddress((void**)&qkv,  g_qkv);
    cudaGetSymbolAddress((void**)&o,    g_o);
    cudaGetSymbolAddress((void**)&wqkv, g_wqkv);
    cudaGetSymbolAddress((void**)&bqkv, g_bqkv);
    cudaGetSymbolAddress((void**)&wo,   g_wo);

    const int SM3 = 3 * (ASTGB + WSTGB);   // 98304
    const int SM2 = 2 * (ASTGB + WSTGB);   // 65536
    cudaFuncSetAttribute(gemm_tc<3,2>,
                         cudaFuncAttributeMaxDynamicSharedMemorySize, SM3);
    cudaFuncSetAttribute(gemm_tc<2,3>,
                         cudaFuncAttributeMaxDynamicSharedMemorySize, SM2);
    cudaFuncSetAttribute(attn_tc,
                         cudaFuncAttributeMaxDynamicSharedMemorySize, ATTN_SMEM);

    // Dest-order vectorized packs
    pack_a_kernel<<<(MT * EMB / 8) / 256, 256>>>(x, gx);
    pack_wqkv_kernel<<<(NQKV * EMB / 4) / 256, 256>>>(Wq, Wk, Wv, bq, bk, bv,
                                                      wqkv, bqkv);
    pack_wo_kernel<<<(EMB * EMB / 4) / 256, 256>>>(Wo, wo);

    // Fused QKV projection: [8192 x 3072], fp16 out — 3-stage, 2 CTA/SM
    gemm_tc<3,2><<<dim3(NQKV / 128, MT / 128), 128, SM3>>>(
        gx, wqkv, bqkv, qkv, NQKV, 1);

    attn_tc<<<dim3(SS / 128, NH, BB), 128, ATTN_SMEM>>>();

    // Output projection: fp32 out — 2-stage, 3 CTA/SM (tail-wave friendly)
    gemm_tc<2,3><<<dim3(EMB / 128, MT / 128), 128, SM2>>>(
        o, wo, bo, d_out, EMB, 0);
}